// round 1
// baseline (speedup 1.0000x reference)
#include <cuda_runtime.h>
#include <math.h>

// Problem constants (fixed shapes)
#define B      2
#define HEADS  8
#define CQ     48
#define CK     12
#define CTOT   384      // HEADS*CQ
#define P      96       // pooled channels = HEADS*CK
#define L      4096
#define TREP   16
#define HW     65536    // 256*256 = TREP*L
#define NROWS  (B*CTOT)     // 768 q rows
#define KROWS  (B*P)        // 192 k rows

// Scratch (static device globals — no allocation)
__device__ float g_qs[NROWS * L];      // folded Q (sum over 16 tiles), raw (un-normalized)
__device__ float g_normq[NROWS];       // ||q row|| over full 65536
__device__ float g_kn[KROWS * L];      // pooled + L2-normalized kv
__device__ float g_attn[NROWS * CK];   // softmax(attn)
__device__ float g_M[B * CTOT * P];    // W folded with attn

__device__ __forceinline__ float warpSum(float v) {
#pragma unroll
    for (int o = 16; o > 0; o >>= 1) v += __shfl_xor_sync(0xffffffffu, v, o);
    return v;
}

// ---------------------------------------------------------------------------
// K1: fold Q over the 16 tile repetitions + compute row L2 norm.
// One block per q-row (768 blocks). Reads 201MB (dominant HBM read).
// ---------------------------------------------------------------------------
__global__ void __launch_bounds__(1024) k_reduce_q(const float* __restrict__ Q) {
    int row = blockIdx.x;
    int tid = threadIdx.x;
    const float4* qp = reinterpret_cast<const float4*>(Q + (size_t)row * HW);
    float4 acc = make_float4(0.f, 0.f, 0.f, 0.f);
    float ss = 0.f;
#pragma unroll
    for (int t = 0; t < TREP; t++) {
        float4 v = qp[t * 1024 + tid];
        acc.x += v.x; acc.y += v.y; acc.z += v.z; acc.w += v.w;
        ss += v.x * v.x + v.y * v.y + v.z * v.z + v.w * v.w;
    }
    reinterpret_cast<float4*>(g_qs + (size_t)row * L)[tid] = acc;

    ss = warpSum(ss);
    __shared__ float sred[32];
    int lane = tid & 31, w = tid >> 5;
    if (lane == 0) sred[w] = ss;
    __syncthreads();
    if (w == 0) {
        float v = sred[lane];
        v = warpSum(v);
        if (lane == 0) g_normq[row] = fmaxf(sqrtf(v), 1e-12f);
    }
}

// ---------------------------------------------------------------------------
// K2: avg_pool1d over channel groups of 4 + L2 normalize each pooled row.
// One block per pooled row (192 blocks).
// ---------------------------------------------------------------------------
__global__ void __launch_bounds__(1024) k_pool_kv(const float* __restrict__ kv) {
    int row = blockIdx.x;               // b*P + i
    int b = row / P, i = row % P;
    int tid = threadIdx.x;
    const float4* base = reinterpret_cast<const float4*>(kv + ((size_t)b * CTOT + 4 * i) * L);
    float4 v0 = base[tid];
    float4 v1 = base[1024 + tid];
    float4 v2 = base[2048 + tid];
    float4 v3 = base[3072 + tid];
    float4 p;
    p.x = 0.25f * (v0.x + v1.x + v2.x + v3.x);
    p.y = 0.25f * (v0.y + v1.y + v2.y + v3.y);
    p.z = 0.25f * (v0.z + v1.z + v2.z + v3.z);
    p.w = 0.25f * (v0.w + v1.w + v2.w + v3.w);
    float ss = p.x * p.x + p.y * p.y + p.z * p.z + p.w * p.w;

    ss = warpSum(ss);
    __shared__ float sred[32];
    __shared__ float s_scale;
    int lane = tid & 31, w = tid >> 5;
    if (lane == 0) sred[w] = ss;
    __syncthreads();
    if (w == 0) {
        float v = sred[lane];
        v = warpSum(v);
        if (lane == 0) s_scale = 1.f / fmaxf(sqrtf(v), 1e-12f);
    }
    __syncthreads();
    float sc = s_scale;
    p.x *= sc; p.y *= sc; p.z *= sc; p.w *= sc;
    reinterpret_cast<float4*>(g_kn + (size_t)row * L)[tid] = p;
}

// ---------------------------------------------------------------------------
// K3: attn logits (12 dots of length 4096 per q-row) / norm, softmax over 12.
// 4 q-rows per block so the 12 kn rows are amortized. 192 blocks x 128 thr.
// ---------------------------------------------------------------------------
__global__ void __launch_bounds__(128) k_attn() {
    int row0 = blockIdx.x * 4;          // 4 rows share (b,h) since CQ%4==0
    int b = row0 / CTOT;
    int rr = row0 % CTOT;
    int h = rr / CQ;
    int tid = threadIdx.x;
    int lane = tid & 31, w = tid >> 5;

    const float* kb = g_kn + ((size_t)b * P + h * CK) * L;
    float acc[4][CK];
#pragma unroll
    for (int r = 0; r < 4; r++)
#pragma unroll
        for (int kk = 0; kk < CK; kk++) acc[r][kk] = 0.f;

    for (int j4 = tid; j4 < 1024; j4 += 128) {
        float4 qv[4];
#pragma unroll
        for (int r = 0; r < 4; r++)
            qv[r] = reinterpret_cast<const float4*>(g_qs + (size_t)(row0 + r) * L)[j4];
#pragma unroll
        for (int kk = 0; kk < CK; kk++) {
            float4 kvv = reinterpret_cast<const float4*>(kb + (size_t)kk * L)[j4];
#pragma unroll
            for (int r = 0; r < 4; r++)
                acc[r][kk] += qv[r].x * kvv.x + qv[r].y * kvv.y +
                              qv[r].z * kvv.z + qv[r].w * kvv.w;
        }
    }

    __shared__ float sp[4][4][CK];      // [warp][r][kk]
#pragma unroll
    for (int r = 0; r < 4; r++)
#pragma unroll
        for (int kk = 0; kk < CK; kk++) {
            float v = warpSum(acc[r][kk]);
            if (lane == 0) sp[w][r][kk] = v;
        }
    __syncthreads();

    __shared__ float logits[4][CK];
    if (tid < 48) {
        int r = tid / CK, kk = tid % CK;
        float d = sp[0][r][kk] + sp[1][r][kk] + sp[2][r][kk] + sp[3][r][kk];
        logits[r][kk] = d / g_normq[row0 + r];
    }
    __syncthreads();
    if (tid < 48) {
        int r = tid / CK, kk = tid % CK;
        float mx = -1e30f;
#pragma unroll
        for (int k2 = 0; k2 < CK; k2++) mx = fmaxf(mx, logits[r][k2]);
        float sum = 0.f;
#pragma unroll
        for (int k2 = 0; k2 < CK; k2++) sum += expf(logits[r][k2] - mx);
        g_attn[(size_t)(row0 + r) * CK + kk] = expf(logits[r][kk] - mx) / sum;
    }
}

// ---------------------------------------------------------------------------
// K4: fold W with attn:  M[b,o,h*12+kk] = sum_cq W[o, h*48+cq] * attn[b,h,cq,kk]
// ---------------------------------------------------------------------------
__global__ void k_fold_w(const float* __restrict__ W) {
    int idx = blockIdx.x * blockDim.x + threadIdx.x;
    if (idx >= B * CTOT * P) return;
    int kk = idx % CK;
    int h  = (idx / CK) % HEADS;
    int o  = (idx / P) % CTOT;
    int b  = idx / (CTOT * P);
    const float* wrow = W + (size_t)o * CTOT + h * CQ;
    const float* arow = g_attn + ((size_t)b * CTOT + h * CQ) * CK + kk;
    float s = 0.f;
#pragma unroll 4
    for (int c = 0; c < CQ; c++) s += wrow[c] * arow[(size_t)c * CK];
    g_M[idx] = s;
}

// ---------------------------------------------------------------------------
// K5: f[b,o,j] = sum_p M[b,o,p] * kn[b,p,j], then write each value to all 16
// tile replicas of the output. Writes 201MB (dominant HBM write).
// Grid (jt=8, ot=24, b=2) = 384 blocks, 128 threads.
// Block tile: 16 o-rows x 512 j-cols (4 j per thread, float4).
// ---------------------------------------------------------------------------
__global__ void __launch_bounds__(128) k_out(float* __restrict__ out) {
    __shared__ float sM[16 * P];
    int jt = blockIdx.x, ot = blockIdx.y, b = blockIdx.z;
    int tid = threadIdx.x;

    const float* Mb = g_M + ((size_t)b * CTOT + ot * 16) * P;
    for (int i = tid; i < 16 * P; i += 128) sM[i] = Mb[i];
    __syncthreads();

    int j = jt * 512 + tid * 4;
    const float* knb = g_kn + (size_t)b * P * L + j;

    float4 acc[16];
#pragma unroll
    for (int oi = 0; oi < 16; oi++) acc[oi] = make_float4(0.f, 0.f, 0.f, 0.f);

#pragma unroll 4
    for (int pg = 0; pg < P; pg += 4) {
        float4 k0 = *reinterpret_cast<const float4*>(knb + (size_t)(pg + 0) * L);
        float4 k1 = *reinterpret_cast<const float4*>(knb + (size_t)(pg + 1) * L);
        float4 k2 = *reinterpret_cast<const float4*>(knb + (size_t)(pg + 2) * L);
        float4 k3 = *reinterpret_cast<const float4*>(knb + (size_t)(pg + 3) * L);
#pragma unroll
        for (int oi = 0; oi < 16; oi++) {
            float4 m = *reinterpret_cast<const float4*>(&sM[oi * P + pg]);
            acc[oi].x += m.x * k0.x + m.y * k1.x + m.z * k2.x + m.w * k3.x;
            acc[oi].y += m.x * k0.y + m.y * k1.y + m.z * k2.y + m.w * k3.y;
            acc[oi].z += m.x * k0.z + m.y * k1.z + m.z * k2.z + m.w * k3.z;
            acc[oi].w += m.x * k0.w + m.y * k1.w + m.z * k2.w + m.w * k3.w;
        }
    }

#pragma unroll
    for (int oi = 0; oi < 16; oi++) {
        size_t base = ((size_t)(b * CTOT + ot * 16 + oi)) * HW + j;
        float4 v = acc[oi];
#pragma unroll
        for (int t = 0; t < TREP; t++)
            *reinterpret_cast<float4*>(out + base + (size_t)t * L) = v;
    }
}

// ---------------------------------------------------------------------------
extern "C" void kernel_launch(void* const* d_in, const int* in_sizes, int n_in,
                              void* d_out, int out_size) {
    const float* Q  = (const float*)d_in[0];
    const float* kv = (const float*)d_in[1];
    const float* W  = (const float*)d_in[2];
    float* out = (float*)d_out;

    k_reduce_q<<<NROWS, 1024>>>(Q);
    k_pool_kv<<<KROWS, 1024>>>(kv);
    k_attn<<<NROWS / 4, 128>>>();
    k_fold_w<<<(B * CTOT * P + 255) / 256, 256>>>(W);
    dim3 g5(8, 24, 2);
    k_out<<<g5, 128>>>(out);
}